// round 3
// baseline (speedup 1.0000x reference)
#include <cuda_runtime.h>
#include <cuda_bf16.h>
#include <cstdint>

// YOLO layer: (B, 3*85, 76, 76) fp32 -> (B, 3*76*76, 85) fp32
// HBM-bound transpose + elementwise epilogue.
//
// Per CTA: TWO grid-rows (2t, 2t+1) of one (batch, anchor), ping-pong buffered:
//   row0: vec4 loads -> transform -> smem buf0 (output order)
//   sync; commit cp.async.bulk(buf0) WITHOUT waiting   <-- overlaps with row1
//   row1: vec4 loads -> transform -> smem buf1
//   sync; commit cp.async.bulk(buf1); wait_group 0 once at the end.
// 512 threads, 51.7KB smem -> 4 CTAs/SM = 2048 threads/SM (full).

#define G     76
#define C     85
#define NA    3
#define TPB   512
#define TILE  (C * G)         // 6460 floats per row-tile (25840 B)
#define TILE4 (TILE / 4)      // 1615 vec4
#define VPC   (G / 4)         // 19 vec4 per channel row
#define HP    (G / 2)         // 38 row-pairs

__device__ __forceinline__ float sigf(float v) {
    return __fdividef(1.0f, 1.0f + __expf(-v));
}

__device__ __forceinline__ void process_row(const float* __restrict__ base,
                                            float* __restrict__ buf,
                                            float stride, float gy,
                                            float aw, float ah)
{
    #pragma unroll 2
    for (unsigned i = threadIdx.x; i < TILE4; i += TPB) {
        const unsigned k = i / VPC;        // channel 0..84
        const unsigned q = i - k * VPC;    // vec4 index 0..18
        const float4 v = __ldcs((const float4*)(base + (size_t)k * (G * G)) + q);
        const int s0 = q * 4;

        float r0, r1, r2, r3;
        if (k >= 4) {
            r0 = sigf(v.x); r1 = sigf(v.y); r2 = sigf(v.z); r3 = sigf(v.w);
        } else if (k == 0) {
            r0 = (sigf(v.x) + (float)(s0 + 0)) * stride;
            r1 = (sigf(v.y) + (float)(s0 + 1)) * stride;
            r2 = (sigf(v.z) + (float)(s0 + 2)) * stride;
            r3 = (sigf(v.w) + (float)(s0 + 3)) * stride;
        } else if (k == 1) {
            r0 = (sigf(v.x) + gy) * stride;
            r1 = (sigf(v.y) + gy) * stride;
            r2 = (sigf(v.z) + gy) * stride;
            r3 = (sigf(v.w) + gy) * stride;
        } else if (k == 2) {
            r0 = __expf(v.x) * aw; r1 = __expf(v.y) * aw;
            r2 = __expf(v.z) * aw; r3 = __expf(v.w) * aw;
        } else {
            r0 = __expf(v.x) * ah; r1 = __expf(v.y) * ah;
            r2 = __expf(v.z) * ah; r3 = __expf(v.w) * ah;
        }
        float* p = &buf[(unsigned)s0 * C + k];   // stride 85: conflict-free
        p[0]     = r0;
        p[C]     = r1;
        p[2 * C] = r2;
        p[3 * C] = r3;
    }
}

__device__ __forceinline__ void commit_store(float* gdst, const float* sbuf)
{
    uint32_t saddr;
    asm("{ .reg .u64 t0; cvta.to.shared.u64 t0, %1; cvt.u32.u64 %0, t0; }"
        : "=r"(saddr) : "l"(sbuf));
    asm volatile("fence.proxy.async.shared::cta;" ::: "memory");
    asm volatile("cp.async.bulk.global.shared::cta.bulk_group [%0], [%1], %2;"
                 :: "l"(gdst), "r"(saddr), "n"(TILE * 4) : "memory");
    asm volatile("cp.async.bulk.commit_group;" ::: "memory");
}

__global__ __launch_bounds__(TPB)
void yolo_kernel(const float* __restrict__ in,
                 const void*  __restrict__ imgdim_p,
                 float* __restrict__ out)
{
    __shared__ __align__(16) float buf0[TILE];
    __shared__ __align__(16) float buf1[TILE];

    const int blk = blockIdx.x;
    const int tp  = blk % HP;             // row pair 0..37
    const int a   = (blk / HP) % NA;      // anchor
    const int b   = blk / (HP * NA);      // batch
    const int t0  = 2 * tp;

    float stride = 8.0f;
    if (imgdim_p) {
        int iv = *(const int*)imgdim_p;
        float dim = (iv > 0 && iv < (1 << 20)) ? (float)iv : __int_as_float(iv);
        stride = dim / (float)G;
    }

    const float AW[NA] = {116.0f, 156.0f, 373.0f};
    const float AH[NA] = { 90.0f, 198.0f, 326.0f};
    const float aw = AW[a], ah = AH[a];

    const float* base0 = in + ((size_t)(b * NA + a) * C) * (G * G) + (size_t)t0 * G;
    float* obase0 = out + ((size_t)(b * NA + a) * (G * G) + (size_t)t0 * G) * C;

    // --- row 0 ---
    process_row(base0, buf0, stride, (float)t0, aw, ah);
    __syncthreads();
    if (threadIdx.x == 0) commit_store(obase0, buf0);   // no wait: overlaps row1

    // --- row 1 ---
    process_row(base0 + G, buf1, stride, (float)(t0 + 1), aw, ah);
    __syncthreads();
    if (threadIdx.x == 0) {
        commit_store(obase0 + TILE, buf1);
        asm volatile("cp.async.bulk.wait_group 0;" ::: "memory");
    }
}

extern "C" void kernel_launch(void* const* d_in, const int* in_sizes, int n_in,
                              void* d_out, int out_size)
{
    const float* x = (const float*)d_in[0];
    const void*  dim = (n_in > 1) ? d_in[1] : nullptr;
    const int B = in_sizes[0] / (NA * C * G * G);   // 64 for the bench shape

    dim3 grid(B * NA * HP);
    yolo_kernel<<<grid, TPB>>>(x, dim, (float*)d_out);
}